// round 15
// baseline (speedup 1.0000x reference)
#include <cuda_runtime.h>

#define NB    32
#define NMEL  128
#define TT    8192
#define NKEYS 88
#define NSLOT 57

// 57 distinct mel bins used by the 88 keys (validated rel_err 0.0, R1..R13)
__device__ constexpr int DBIN[NSLOT] = {
   1,  2,  3,  4,  5,  6,  7,  8,  9, 10, 11, 12, 13, 14, 15, 16, 17,
  19, 20, 21, 22, 23, 25, 26, 28, 29, 31, 33, 35, 37, 39, 42,
  44, 46, 49, 51, 53, 56, 58, 60, 63,
  65, 68, 70, 72, 75, 77, 79, 82, 84, 86, 89, 91, 93, 96, 98, 101
};

// key -> distinct-slot index (non-decreasing)
__device__ constexpr int KS[NKEYS] = {
   0, 0, 0, 0, 0,
   1, 1, 1, 1, 1, 1, 1, 1, 1,
   2, 2, 2, 2, 2, 2,
   3, 3, 3, 3,
   4, 4, 4,  5, 5, 5,  6, 6, 6,
   7, 7,  8, 8,  9, 9,
  10, 11, 11, 12, 13, 14, 15, 16, 16,
  17, 18, 19, 20, 21, 22, 23, 24, 25, 26, 27, 28, 29, 30, 31, 32,
  33, 34, 35, 36, 37, 38, 39, 40, 41, 42, 43, 44, 45, 46, 47, 48,
  49, 50, 51, 52, 53, 54, 55, 56
};

// slot -> [first key, last key)
__device__ constexpr int KST[NSLOT + 1] = {
   0,  5, 14, 20, 24, 27, 30, 33, 35, 37, 39, 40, 42, 43, 44, 45, 46, 48,
  49, 50, 51, 52, 53, 54, 55, 56, 57, 58, 59, 60, 61, 62, 63, 64, 65, 66,
  67, 68, 69, 70, 71, 72, 73, 74, 75, 76, 77, 78, 79, 80, 81, 82, 83, 84,
  85, 86, 87, 88
};

template <bool WRITE_TWO>
__global__ void __launch_bounds__(128, 5)
hps_key_probs_kernel(const float* __restrict__ mel,
                     float* __restrict__ out)
{
    const int p = blockIdx.x * 128 + threadIdx.x;   // 0..262143
    const int b = p >> 13;
    const int t = p & (TT - 1);

    const float* __restrict__ mb = mel + (size_t)b * (NMEL * TT) + t;

    // ---- Load all 57 distinct slot values into registers (log-domain HPS:
    // m[bin] (+ m[2bin]) (+ m[3bin]); exp dropped by monotonicity, validated).
    // __ldcs: single-use data, evict-first keeps L2 free for the write stream.
    float w[NSLOT];
    #pragma unroll
    for (int j = 0; j < NSLOT; ++j) {
        const int bn = DBIN[j];
        float s = __ldcs(mb + (size_t)bn * TT);
        if (bn < 64) s += __ldcs(mb + (size_t)(2 * bn) * TT);
        if (bn < 43) s += __ldcs(mb + (size_t)(3 * bn) * TT);
        w[j] = s;
    }

    float tt[16], g[16];

    // ---- Streaming selection of the 14th-largest of the 88-multiset.
    // Groups 0..4: 16 keys each.
    #pragma unroll
    for (int grp = 0; grp < 5; ++grp) {
        #pragma unroll
        for (int u = 0; u < 16; ++u) g[u] = w[KS[grp * 16 + u]];
        // bitonic sort-16 descending (compile-time lanes)
        #pragma unroll
        for (int kk = 2; kk <= 16; kk <<= 1) {
            #pragma unroll
            for (int j = kk >> 1; j > 0; j >>= 1) {
                #pragma unroll
                for (int i = 0; i < 16; ++i) {
                    const int l = i ^ j;
                    if (l > i) {
                        const float a = g[i], c = g[l];
                        if ((i & kk) == 0) { g[i] = fmaxf(a, c); g[l] = fminf(a, c); }
                        else               { g[i] = fminf(a, c); g[l] = fmaxf(a, c); }
                    }
                }
            }
        }
        if (grp == 0) {
            #pragma unroll
            for (int i = 0; i < 16; ++i) tt[i] = g[i];
        } else {
            // merge-keep-top-16: max vs reversed g (bitonic) then clean
            #pragma unroll
            for (int i = 0; i < 16; ++i) tt[i] = fmaxf(tt[i], g[15 - i]);
            #pragma unroll
            for (int j = 8; j > 0; j >>= 1) {
                #pragma unroll
                for (int i = 0; i < 16; ++i) {
                    const int l = i ^ j;
                    if (l > i) {
                        const float a = tt[i], c = tt[l];
                        tt[i] = fmaxf(a, c); tt[l] = fminf(a, c);
                    }
                }
            }
        }
    }

    // Tail group: 8 keys (80..87) -> sort-8, asym merge, rank-13 extraction
    // (validated rel_err 0.0, R6..R13).
    float cut;
    {
        #pragma unroll
        for (int u = 0; u < 8; ++u) g[u] = w[KS[80 + u]];
        #pragma unroll
        for (int kk = 2; kk <= 8; kk <<= 1) {
            #pragma unroll
            for (int j = kk >> 1; j > 0; j >>= 1) {
                #pragma unroll
                for (int i = 0; i < 8; ++i) {
                    const int l = i ^ j;
                    if (l > i) {
                        const float a = g[i], c = g[l];
                        if ((i & kk) == 0) { g[i] = fmaxf(a, c); g[l] = fminf(a, c); }
                        else               { g[i] = fminf(a, c); g[l] = fmaxf(a, c); }
                    }
                }
            }
        }
        // positions 8..15 absorb g[7..0]; 0..7 unchanged (pad = -inf)
        #pragma unroll
        for (int i = 8; i < 16; ++i) tt[i] = fmaxf(tt[i], g[15 - i]);
        // tt bitonic; descend to rank 13 (14th largest)
        float l8[8];
        #pragma unroll
        for (int i = 0; i < 8; ++i) l8[i] = fminf(tt[i], tt[i + 8]);
        float l4[4];
        #pragma unroll
        for (int i = 0; i < 4; ++i) l4[i] = fminf(l8[i], l8[i + 4]);
        const float p0 = fmaxf(l4[0], l4[2]);
        const float p1 = fmaxf(l4[1], l4[3]);
        cut = fminf(p0, p1);
    }

    float* o0 = out + (size_t)b * (NKEYS * TT) + t;
    const size_t half = (size_t)NB * NKEYS * TT;

    // ---- Output: one compare per slot, fan out to contiguous keys, both
    // copies (compile-time). __stwt: write-through — output is write-once /
    // never-read, so skip dirty-L2 residency and shorten the drain path.
    #pragma unroll
    for (int j = 0; j < NSLOT; ++j) {
        const float pv = (w[j] >= cut) ? 1.0f : 0.0f;
        #pragma unroll
        for (int k = KST[j]; k < KST[j + 1]; ++k) {
            __stwt(o0 + (size_t)k * TT, pv);
            if (WRITE_TWO) __stwt(o0 + (size_t)k * TT + half, pv);
        }
    }
}

extern "C" void kernel_launch(void* const* d_in, const int* in_sizes, int n_in,
                              void* d_out, int out_size)
{
    const float* mel = (const float*)d_in[0];
    float* out = (float*)d_out;
    const long long half = (long long)NB * NKEYS * TT;   // 23,068,672
    const int points = NB * TT;                          // 262144

    if (out_size >= 2 * half)
        hps_key_probs_kernel<true><<<points / 128, 128>>>(mel, out);
    else
        hps_key_probs_kernel<false><<<points / 128, 128>>>(mel, out);
}

// round 16
// speedup vs baseline: 1.0050x; 1.0050x over previous
#include <cuda_runtime.h>

#define NB    32
#define NMEL  128
#define TT    8192
#define NKEYS 88
#define NSLOT 57

// 57 distinct mel bins used by the 88 keys (validated rel_err 0.0, R1..R14)
__device__ constexpr int DBIN[NSLOT] = {
   1,  2,  3,  4,  5,  6,  7,  8,  9, 10, 11, 12, 13, 14, 15, 16, 17,
  19, 20, 21, 22, 23, 25, 26, 28, 29, 31, 33, 35, 37, 39, 42,
  44, 46, 49, 51, 53, 56, 58, 60, 63,
  65, 68, 70, 72, 75, 77, 79, 82, 84, 86, 89, 91, 93, 96, 98, 101
};

// key -> distinct-slot index (non-decreasing)
__device__ constexpr int KS[NKEYS] = {
   0, 0, 0, 0, 0,
   1, 1, 1, 1, 1, 1, 1, 1, 1,
   2, 2, 2, 2, 2, 2,
   3, 3, 3, 3,
   4, 4, 4,  5, 5, 5,  6, 6, 6,
   7, 7,  8, 8,  9, 9,
  10, 11, 11, 12, 13, 14, 15, 16, 16,
  17, 18, 19, 20, 21, 22, 23, 24, 25, 26, 27, 28, 29, 30, 31, 32,
  33, 34, 35, 36, 37, 38, 39, 40, 41, 42, 43, 44, 45, 46, 47, 48,
  49, 50, 51, 52, 53, 54, 55, 56
};

// slot -> [first key, last key)
__device__ constexpr int KST[NSLOT + 1] = {
   0,  5, 14, 20, 24, 27, 30, 33, 35, 37, 39, 40, 42, 43, 44, 45, 46, 48,
  49, 50, 51, 52, 53, 54, 55, 56, 57, 58, 59, 60, 61, 62, 63, 64, 65, 66,
  67, 68, 69, 70, 71, 72, 73, 74, 75, 76, 77, 78, 79, 80, 81, 82, 83, 84,
  85, 86, 87, 88
};

template <bool WRITE_TWO>
__global__ void __launch_bounds__(128, 5)
hps_key_probs_kernel(const float* __restrict__ mel,
                     float* __restrict__ out)
{
    const int p = blockIdx.x * 128 + threadIdx.x;   // 0..262143
    const int b = p >> 13;
    const int t = p & (TT - 1);

    const float* __restrict__ mb = mel + (size_t)b * (NMEL * TT) + t;

    // ---- Load all 57 distinct slot values into registers (log-domain HPS:
    // m[bin] (+ m[2bin]) (+ m[3bin]); exp dropped by monotonicity, validated).
    // __ldlu: strict read-once data -> last-use policy, release L1 lines
    // immediately so the cache serves the store stream.
    float w[NSLOT];
    #pragma unroll
    for (int j = 0; j < NSLOT; ++j) {
        const int bn = DBIN[j];
        float s = __ldlu(mb + (size_t)bn * TT);
        if (bn < 64) s += __ldlu(mb + (size_t)(2 * bn) * TT);
        if (bn < 43) s += __ldlu(mb + (size_t)(3 * bn) * TT);
        w[j] = s;
    }

    float tt[16], g[16];

    // ---- Streaming selection of the 14th-largest of the 88-multiset.
    // Groups 0..4: 16 keys each.
    #pragma unroll
    for (int grp = 0; grp < 5; ++grp) {
        #pragma unroll
        for (int u = 0; u < 16; ++u) g[u] = w[KS[grp * 16 + u]];
        // bitonic sort-16 descending (compile-time lanes)
        #pragma unroll
        for (int kk = 2; kk <= 16; kk <<= 1) {
            #pragma unroll
            for (int j = kk >> 1; j > 0; j >>= 1) {
                #pragma unroll
                for (int i = 0; i < 16; ++i) {
                    const int l = i ^ j;
                    if (l > i) {
                        const float a = g[i], c = g[l];
                        if ((i & kk) == 0) { g[i] = fmaxf(a, c); g[l] = fminf(a, c); }
                        else               { g[i] = fminf(a, c); g[l] = fmaxf(a, c); }
                    }
                }
            }
        }
        if (grp == 0) {
            #pragma unroll
            for (int i = 0; i < 16; ++i) tt[i] = g[i];
        } else {
            // merge-keep-top-16: max vs reversed g (bitonic) then clean
            #pragma unroll
            for (int i = 0; i < 16; ++i) tt[i] = fmaxf(tt[i], g[15 - i]);
            #pragma unroll
            for (int j = 8; j > 0; j >>= 1) {
                #pragma unroll
                for (int i = 0; i < 16; ++i) {
                    const int l = i ^ j;
                    if (l > i) {
                        const float a = tt[i], c = tt[l];
                        tt[i] = fmaxf(a, c); tt[l] = fminf(a, c);
                    }
                }
            }
        }
    }

    // Tail group: 8 keys (80..87) -> sort-8, asym merge, rank-13 extraction
    // (validated rel_err 0.0, R6..R14).
    float cut;
    {
        #pragma unroll
        for (int u = 0; u < 8; ++u) g[u] = w[KS[80 + u]];
        #pragma unroll
        for (int kk = 2; kk <= 8; kk <<= 1) {
            #pragma unroll
            for (int j = kk >> 1; j > 0; j >>= 1) {
                #pragma unroll
                for (int i = 0; i < 8; ++i) {
                    const int l = i ^ j;
                    if (l > i) {
                        const float a = g[i], c = g[l];
                        if ((i & kk) == 0) { g[i] = fmaxf(a, c); g[l] = fminf(a, c); }
                        else               { g[i] = fminf(a, c); g[l] = fmaxf(a, c); }
                    }
                }
            }
        }
        // positions 8..15 absorb g[7..0]; 0..7 unchanged (pad = -inf)
        #pragma unroll
        for (int i = 8; i < 16; ++i) tt[i] = fmaxf(tt[i], g[15 - i]);
        // tt bitonic; descend to rank 13 (14th largest)
        float l8[8];
        #pragma unroll
        for (int i = 0; i < 8; ++i) l8[i] = fminf(tt[i], tt[i + 8]);
        float l4[4];
        #pragma unroll
        for (int i = 0; i < 4; ++i) l4[i] = fminf(l8[i], l8[i + 4]);
        const float p0 = fmaxf(l4[0], l4[2]);
        const float p1 = fmaxf(l4[1], l4[3]);
        cut = fminf(p0, p1);
    }

    float* o0 = out + (size_t)b * (NKEYS * TT) + t;
    const size_t half = (size_t)NB * NKEYS * TT;

    // ---- Output: one compare per slot, fan out to contiguous keys, both
    // copies (compile-time). __stwt: write-through — output is write-once /
    // never-read; skip dirty-L2 residency (validated win in R14).
    #pragma unroll
    for (int j = 0; j < NSLOT; ++j) {
        const float pv = (w[j] >= cut) ? 1.0f : 0.0f;
        #pragma unroll
        for (int k = KST[j]; k < KST[j + 1]; ++k) {
            __stwt(o0 + (size_t)k * TT, pv);
            if (WRITE_TWO) __stwt(o0 + (size_t)k * TT + half, pv);
        }
    }
}

extern "C" void kernel_launch(void* const* d_in, const int* in_sizes, int n_in,
                              void* d_out, int out_size)
{
    const float* mel = (const float*)d_in[0];
    float* out = (float*)d_out;
    const long long half = (long long)NB * NKEYS * TT;   // 23,068,672
    const int points = NB * TT;                          // 262144

    if (out_size >= 2 * half)
        hps_key_probs_kernel<true><<<points / 128, 128>>>(mel, out);
    else
        hps_key_probs_kernel<false><<<points / 128, 128>>>(mel, out);
}